// round 8
// baseline (speedup 1.0000x reference)
#include <cuda_runtime.h>

// ---------------- device scratch ----------------
__device__ __align__(16) float g_act0[32 * 21504];
__device__ __align__(16) float g_act1[32 * 16384];
__device__ __align__(16) float g_act2[32 * 4096];
__device__ __align__(16) float g_act3[32 * 4096];
__device__ __align__(16) float g_act4[32 * 64];
__device__ __align__(16) float g_part[4 * 32 * 4096];

// ---------------- PTX helpers ----------------
__device__ __forceinline__ void ldsm4(unsigned &r0, unsigned &r1, unsigned &r2, unsigned &r3, unsigned a) {
    asm volatile("ldmatrix.sync.aligned.m8n8.x4.shared.b16 {%0,%1,%2,%3}, [%4];"
                 : "=r"(r0), "=r"(r1), "=r"(r2), "=r"(r3) : "r"(a));
}
__device__ __forceinline__ void mma16816(float* d, unsigned a0, unsigned a1, unsigned a2, unsigned a3,
                                         unsigned b0, unsigned b1) {
    asm volatile("mma.sync.aligned.m16n8k16.row.col.f32.bf16.bf16.f32 "
                 "{%0,%1,%2,%3}, {%4,%5,%6,%7}, {%8,%9}, {%0,%1,%2,%3};"
                 : "+f"(d[0]), "+f"(d[1]), "+f"(d[2]), "+f"(d[3])
                 : "r"(a0), "r"(a1), "r"(a2), "r"(a3), "r"(b0), "r"(b1));
}
// float4 -> bf16 hi pair-regs + lo pair-regs
__device__ __forceinline__ void cvt_hilo(float4 v, unsigned &h01, unsigned &h23,
                                         unsigned &l01, unsigned &l23) {
    asm("cvt.rn.bf16x2.f32 %0, %1, %2;" : "=r"(h01) : "f"(v.y), "f"(v.x));
    asm("cvt.rn.bf16x2.f32 %0, %1, %2;" : "=r"(h23) : "f"(v.w), "f"(v.z));
    float r0 = v.x - __uint_as_float(h01 << 16);
    float r1 = v.y - __uint_as_float(h01 & 0xffff0000u);
    float r2 = v.z - __uint_as_float(h23 << 16);
    float r3 = v.w - __uint_as_float(h23 & 0xffff0000u);
    asm("cvt.rn.bf16x2.f32 %0, %1, %2;" : "=r"(l01) : "f"(r1), "f"(r0));
    asm("cvt.rn.bf16x2.f32 %0, %1, %2;" : "=r"(l23) : "f"(r3), "f"(r2));
}
__device__ __forceinline__ void sts8(unsigned a, unsigned r0, unsigned r1) {
    asm volatile("st.shared.v2.b32 [%0], {%1,%2};" :: "r"(a), "r"(r0), "r"(r1));
}

// tile geometry: M=128 neurons x N=32 batch, K-slab = 128
// bf16 tiles: row stride 136 elements (272 B) -> LDSM conflict-free
#define TS2      272                 // row stride bytes
#define WH_OFF   0                   // 128 * 272 = 34816
#define WL_OFF   34816
#define XH_OFF   69632               // 32 * 272 = 8704
#define XL_OFF   78336
#define BUF_SZ   87040
#define SMEM_TOTAL (2 * BUF_SZ)      // 174080

// ---------------- conv + permuted scatter ----------------
__global__ void conv_kernel(const float* __restrict__ in,
                            const float* __restrict__ cw,
                            const float* __restrict__ cb) {
    int b = blockIdx.x >> 2, f = blockIdx.x & 3, tid = threadIdx.x;
    __shared__ float xin[343], wsh[128], bsh[16];
    for (int i = tid; i < 343; i += 128) xin[i] = in[(b * 343 + i) * 5 + f];
    if (tid < 128) wsh[tid] = cw[tid];
    if (tid < 16)  bsh[tid] = cb[tid];
    __syncthreads();
    int h = b >> 4, base = (b & 15) * 1344 + f * 336;
    for (int l = tid; l < 336; l += 128) {
        #pragma unroll
        for (int c = 0; c < 16; ++c) {
            float s = bsh[c];
            #pragma unroll
            for (int k = 0; k < 8; ++k) s += xin[l + k] * wsh[c * 8 + k];
            g_act0[(2 * c + h) * 21504 + base + l] = fmaxf(s, 0.f);
        }
    }
}

// ---------------- bf16x3 mma.sync GEMM, M=128 x N=32, reg-staged ----------------
__device__ __forceinline__ const float* act_in(int s) {
    return s == 0 ? g_act0 : s == 1 ? g_act1 : g_act2;
}

__global__ __launch_bounds__(256)
void gemm_mma(int xsel, const float* __restrict__ W, const float* __restrict__ bias,
              float* __restrict__ outp, int N, int K, int nslabs, int split) {
    extern __shared__ __align__(1024) char smem[];
    unsigned sb = (unsigned)__cvta_generic_to_shared(smem);
    const float* X = act_in(xsel);
    int tid = threadIdx.x, wid = tid >> 5, lane = tid & 31;
    int tile = blockIdx.x, ky = blockIdx.y;
    long k0 = (long)ky * nslabs * 128;

    const float* Wt = W + (long)tile * 128 * K + k0;
    const float* Xt = X + k0;

    // LDG mapping: W row = tid>>1 (2 thr/row, 16 float4 each); X row = tid>>3 (8 thr/row, 4 f4)
    int wrow = tid >> 1, wc4 = (tid & 1) * 16;
    int xrow = tid >> 3, xc4 = (tid & 7) * 4;
    const float* wsrc = Wt + (long)wrow * K + wc4 * 4;
    const float* xsrc = Xt + (long)xrow * K + xc4 * 4;

    float4 wreg[16], xreg[4];
    auto ldg_slab = [&](int s) {
        long koff = (long)s * 128;
        #pragma unroll
        for (int i = 0; i < 16; ++i) wreg[i] = __ldg((const float4*)(wsrc + koff) + i);
        #pragma unroll
        for (int i = 0; i < 4; ++i)  xreg[i] = __ldg((const float4*)(xsrc + koff) + i);
    };
    auto cvt_slab = [&](int buf) {
        unsigned wb = sb + buf * BUF_SZ;
        unsigned wdst = wb + wrow * TS2 + wc4 * 8;
        #pragma unroll
        for (int i = 0; i < 16; ++i) {
            unsigned h01, h23, l01, l23;
            cvt_hilo(wreg[i], h01, h23, l01, l23);
            sts8(wdst + WH_OFF + i * 8, h01, h23);
            sts8(wdst + WL_OFF + i * 8, l01, l23);
        }
        unsigned xdst = wb + xrow * TS2 + xc4 * 8;
        #pragma unroll
        for (int i = 0; i < 4; ++i) {
            unsigned h01, h23, l01, l23;
            cvt_hilo(xreg[i], h01, h23, l01, l23);
            sts8(xdst + XH_OFF + i * 8, h01, h23);
            sts8(xdst + XL_OFF + i * 8, l01, l23);
        }
    };

    // fragment addressing (validated in R6)
    unsigned aoff = (unsigned)((wid * 16 + (lane & 15)) * 136 + (lane >> 4) * 8) * 2;
    unsigned boff = (unsigned)(((lane & 7) + ((lane >> 3) & 1) * 8) * 136 + (lane >> 4) * 8) * 2;
    unsigned boff2 = boff + 16 * TS2;

    float acc[4][4];
    #pragma unroll
    for (int i = 0; i < 4; ++i)
        #pragma unroll
        for (int j = 0; j < 4; ++j) acc[i][j] = 0.f;

    ldg_slab(0);
    for (int s = 0; s < nslabs; ++s) {
        int buf = s & 1;
        cvt_slab(buf);
        __syncthreads();
        if (s + 1 < nslabs) ldg_slab(s + 1);

        unsigned bb = sb + buf * BUF_SZ;
        #pragma unroll
        for (int ks = 0; ks < 8; ++ks) {
            unsigned ko = ks * 32;
            unsigned ah0,ah1,ah2,ah3, al0,al1,al2,al3;
            unsigned p0,p1,p2,p3, q0,q1,q2,q3, r0,r1,r2,r3, s0,s1,s2,s3;
            ldsm4(ah0,ah1,ah2,ah3, bb + WH_OFF + aoff + ko);
            ldsm4(al0,al1,al2,al3, bb + WL_OFF + aoff + ko);
            ldsm4(p0,p1,p2,p3, bb + XH_OFF + boff  + ko);  // X hi, n 0-15
            ldsm4(q0,q1,q2,q3, bb + XH_OFF + boff2 + ko);  // X hi, n 16-31
            ldsm4(r0,r1,r2,r3, bb + XL_OFF + boff  + ko);  // X lo, n 0-15
            ldsm4(s0,s1,s2,s3, bb + XL_OFF + boff2 + ko);  // X lo, n 16-31
            mma16816(acc[0], ah0,ah1,ah2,ah3, p0,p2);
            mma16816(acc[0], ah0,ah1,ah2,ah3, r0,r2);
            mma16816(acc[0], al0,al1,al2,al3, p0,p2);
            mma16816(acc[1], ah0,ah1,ah2,ah3, p1,p3);
            mma16816(acc[1], ah0,ah1,ah2,ah3, r1,r3);
            mma16816(acc[1], al0,al1,al2,al3, p1,p3);
            mma16816(acc[2], ah0,ah1,ah2,ah3, q0,q2);
            mma16816(acc[2], ah0,ah1,ah2,ah3, s0,s2);
            mma16816(acc[2], al0,al1,al2,al3, q0,q2);
            mma16816(acc[3], ah0,ah1,ah2,ah3, q1,q3);
            mma16816(acc[3], ah0,ah1,ah2,ah3, s1,s3);
            mma16816(acc[3], al0,al1,al2,al3, q1,q3);
        }
    }

    // epilogue: acc[nf][0,1] = rows g, cols 2t/2t+1 ; acc[nf][2,3] = rows g+8
    int g = lane >> 2, t = lane & 3;
    int n0 = tile * 128 + wid * 16 + g;
    #pragma unroll
    for (int nf = 0; nf < 4; ++nf) {
        int b0 = nf * 8 + 2 * t;
        if (split) {
            g_part[(long)(ky * 32 + b0)     * N + n0]     = acc[nf][0];
            g_part[(long)(ky * 32 + b0 + 1) * N + n0]     = acc[nf][1];
            g_part[(long)(ky * 32 + b0)     * N + n0 + 8] = acc[nf][2];
            g_part[(long)(ky * 32 + b0 + 1) * N + n0 + 8] = acc[nf][3];
        } else {
            float bv0 = bias[n0], bv8 = bias[n0 + 8];
            outp[(long)b0       * N + n0]     = fmaxf(acc[nf][0] + bv0, 0.f);
            outp[(long)(b0 + 1) * N + n0]     = fmaxf(acc[nf][1] + bv0, 0.f);
            outp[(long)b0       * N + n0 + 8] = fmaxf(acc[nf][2] + bv8, 0.f);
            outp[(long)(b0 + 1) * N + n0 + 8] = fmaxf(acc[nf][3] + bv8, 0.f);
        }
    }
}

// ---------------- split-K reduce + bias + relu ----------------
__global__ void reduce_kernel(const float* __restrict__ bias, int osel, int N, int ks) {
    int idx = blockIdx.x * 256 + threadIdx.x;
    if (idx >= 32 * N) return;
    float s = bias[idx % N];
    for (int si = 0; si < ks; ++si) s += g_part[(long)si * 32 * N + idx];
    float* out = (osel == 2) ? g_act2 : g_act3;
    out[idx] = fmaxf(s, 0.f);
}

// ---------------- dense4 (4096 -> 64) ----------------
__global__ void dense4_kernel(const float* __restrict__ w4, const float* __restrict__ b4) {
    int n = blockIdx.x, tid = threadIdx.x;
    float acc[32];
    #pragma unroll
    for (int b = 0; b < 32; ++b) acc[b] = 0.f;
    const float* wr = w4 + n * 4096;
    for (int k = tid; k < 4096; k += 128) {
        float w = wr[k];
        #pragma unroll
        for (int b = 0; b < 32; ++b) acc[b] += g_act3[b * 4096 + k] * w;
    }
    __shared__ float red[4][32];
    int lane = tid & 31, wrp = tid >> 5;
    #pragma unroll
    for (int b = 0; b < 32; ++b) {
        float v = acc[b];
        v += __shfl_down_sync(0xffffffffu, v, 16);
        v += __shfl_down_sync(0xffffffffu, v, 8);
        v += __shfl_down_sync(0xffffffffu, v, 4);
        v += __shfl_down_sync(0xffffffffu, v, 2);
        v += __shfl_down_sync(0xffffffffu, v, 1);
        if (lane == 0) red[wrp][b] = v;
    }
    __syncthreads();
    if (tid < 32) {
        float s = red[0][tid] + red[1][tid] + red[2][tid] + red[3][tid] + b4[n];
        g_act4[tid * 64 + n] = fmaxf(s, 0.f);
    }
}

// ---------------- fused output (64 -> 16 -> 1) ----------------
__global__ void final_kernel(const float* __restrict__ wo, const float* __restrict__ bo,
                             const float* __restrict__ wf, const float* __restrict__ bf,
                             float* __restrict__ out) {
    int b = threadIdx.x;
    float res = bf[0];
    for (int j = 0; j < 16; ++j) {
        float o = bo[j];
        #pragma unroll
        for (int n = 0; n < 64; ++n) o += g_act4[b * 64 + n] * wo[j * 64 + n];
        res += o * wf[j];
    }
    out[b] = res;
}

extern "C" void kernel_launch(void* const* d_in, const int* in_sizes, int n_in,
                              void* d_out, int out_size) {
    const float* in  = (const float*)d_in[0];
    const float* cw  = (const float*)d_in[4];
    const float* cb  = (const float*)d_in[5];
    const float* w1  = (const float*)d_in[6];
    const float* b1  = (const float*)d_in[7];
    const float* w2  = (const float*)d_in[8];
    const float* b2  = (const float*)d_in[9];
    const float* w3  = (const float*)d_in[10];
    const float* b3  = (const float*)d_in[11];
    const float* w4  = (const float*)d_in[12];
    const float* b4  = (const float*)d_in[13];
    const float* wo  = (const float*)d_in[14];
    const float* bo  = (const float*)d_in[15];
    const float* wf  = (const float*)d_in[16];
    const float* bf  = (const float*)d_in[17];
    float* out = (float*)d_out;

    float* act1;
    cudaGetSymbolAddress((void**)&act1, g_act1);

    cudaFuncSetAttribute(gemm_mma, cudaFuncAttributeMaxDynamicSharedMemorySize, SMEM_TOTAL);

    conv_kernel<<<128, 128>>>(in, cw, cb);

    // dense1: 16384x21504 -> 128 M-tiles, no split, 168 slabs
    gemm_mma<<<dim3(128, 1), 256, SMEM_TOTAL>>>(0, w1, b1, act1, 16384, 21504, 168, 0);

    // dense2: 4096x16384 -> 32 tiles x split 4, 32 slabs each
    gemm_mma<<<dim3(32, 4), 256, SMEM_TOTAL>>>(1, w2, nullptr, nullptr, 4096, 16384, 32, 1);
    reduce_kernel<<<512, 256>>>(b2, 2, 4096, 4);

    // dense3: 4096x4096 -> 32 tiles x split 4, 8 slabs each
    gemm_mma<<<dim3(32, 4), 256, SMEM_TOTAL>>>(2, w3, nullptr, nullptr, 4096, 4096, 8, 1);
    reduce_kernel<<<512, 256>>>(b3, 3, 4096, 4);

    dense4_kernel<<<64, 128>>>(w4, b4);
    final_kernel<<<1, 32>>>(wo, bo, wf, bf, out);
}

// round 9
// speedup vs baseline: 1.1383x; 1.1383x over previous
#include <cuda_runtime.h>

// ---------------- device scratch ----------------
__device__ __align__(16) float g_act0[32 * 21504];
__device__ __align__(16) float g_act1[32 * 16384];
__device__ __align__(16) float g_act2[32 * 4096];
__device__ __align__(16) float g_act3[32 * 4096];
__device__ __align__(16) float g_act4[32 * 64];
__device__ __align__(16) float g_part[1048576];   // max(2*32*16384, 8*32*4096)

// ---------------- PTX helpers ----------------
__device__ __forceinline__ void ldsm4(unsigned &r0, unsigned &r1, unsigned &r2, unsigned &r3, unsigned a) {
    asm volatile("ldmatrix.sync.aligned.m8n8.x4.shared.b16 {%0,%1,%2,%3}, [%4];"
                 : "=r"(r0), "=r"(r1), "=r"(r2), "=r"(r3) : "r"(a));
}
__device__ __forceinline__ void mma16816(float* d, unsigned a0, unsigned a1, unsigned a2, unsigned a3,
                                         unsigned b0, unsigned b1) {
    asm volatile("mma.sync.aligned.m16n8k16.row.col.f32.bf16.bf16.f32 "
                 "{%0,%1,%2,%3}, {%4,%5,%6,%7}, {%8,%9}, {%0,%1,%2,%3};"
                 : "+f"(d[0]), "+f"(d[1]), "+f"(d[2]), "+f"(d[3])
                 : "r"(a0), "r"(a1), "r"(a2), "r"(a3), "r"(b0), "r"(b1));
}
__device__ __forceinline__ void cvt_hilo(float4 v, unsigned &h01, unsigned &h23,
                                         unsigned &l01, unsigned &l23) {
    asm("cvt.rn.bf16x2.f32 %0, %1, %2;" : "=r"(h01) : "f"(v.y), "f"(v.x));
    asm("cvt.rn.bf16x2.f32 %0, %1, %2;" : "=r"(h23) : "f"(v.w), "f"(v.z));
    float r0 = v.x - __uint_as_float(h01 << 16);
    float r1 = v.y - __uint_as_float(h01 & 0xffff0000u);
    float r2 = v.z - __uint_as_float(h23 << 16);
    float r3 = v.w - __uint_as_float(h23 & 0xffff0000u);
    asm("cvt.rn.bf16x2.f32 %0, %1, %2;" : "=r"(l01) : "f"(r1), "f"(r0));
    asm("cvt.rn.bf16x2.f32 %0, %1, %2;" : "=r"(l23) : "f"(r3), "f"(r2));
}
__device__ __forceinline__ void sts8(unsigned a, unsigned r0, unsigned r1) {
    asm volatile("st.shared.v2.b32 [%0], {%1,%2};" :: "r"(a), "r"(r0), "r"(r1));
}

// tile geometry: M=128 x N=32, K-slab = 64, row stride 144 B (LDSM conflict-free)
#define TSB      144
#define WH_OFF   0                    // 128*144 = 18432
#define WL_OFF   18432
#define XH_OFF   36864                // 32*144 = 4608
#define XL_OFF   41472
#define BUF_SZ   46080
#define SMEM_TOTAL (2 * BUF_SZ)       // 92160 -> 2 CTAs/SM

// ---------------- conv + permuted scatter ----------------
__global__ void conv_kernel(const float* __restrict__ in,
                            const float* __restrict__ cw,
                            const float* __restrict__ cb) {
    int b = blockIdx.x >> 2, f = blockIdx.x & 3, tid = threadIdx.x;
    __shared__ float xin[343], wsh[128], bsh[16];
    for (int i = tid; i < 343; i += 128) xin[i] = in[(b * 343 + i) * 5 + f];
    if (tid < 128) wsh[tid] = cw[tid];
    if (tid < 16)  bsh[tid] = cb[tid];
    __syncthreads();
    int h = b >> 4, base = (b & 15) * 1344 + f * 336;
    for (int l = tid; l < 336; l += 128) {
        #pragma unroll
        for (int c = 0; c < 16; ++c) {
            float s = bsh[c];
            #pragma unroll
            for (int k = 0; k < 8; ++k) s += xin[l + k] * wsh[c * 8 + k];
            g_act0[(2 * c + h) * 21504 + base + l] = fmaxf(s, 0.f);
        }
    }
}

// ---------------- bf16x3 mma.sync GEMM, M=128 x N=32, KS=64, 2 CTA/SM ----------------
__device__ __forceinline__ const float* act_in(int s) {
    return s == 0 ? g_act0 : s == 1 ? g_act1 : g_act2;
}

__global__ __launch_bounds__(256, 2)
void gemm_mma(int xsel, const float* __restrict__ W, float* __restrict__ outp,
              int N, int K, int nslabs) {
    extern __shared__ __align__(1024) char smem[];
    unsigned sb = (unsigned)__cvta_generic_to_shared(smem);
    const float* X = act_in(xsel);
    int tid = threadIdx.x, wid = tid >> 5, lane = tid & 31;
    int tile = blockIdx.x, ky = blockIdx.y;
    long k0 = (long)ky * nslabs * 64;

    const float* Wt = W + (long)tile * 128 * K + k0;
    const float* Xt = X + k0;

    // LDG mapping: W row = tid>>1 (2 thr/row, 8 f4 each); X row = tid>>3 (8 thr/row, 2 f4)
    int wrow = tid >> 1, wf4 = (tid & 1) * 8;
    int xrow = tid >> 3, xf4 = (tid & 7) * 2;
    const float* wsrc = Wt + (long)wrow * K + wf4 * 4;
    const float* xsrc = Xt + (long)xrow * K + xf4 * 4;

    float4 wreg[8], xreg[2];
    auto ldg_slab = [&](int s) {
        long koff = (long)s * 64;
        #pragma unroll
        for (int i = 0; i < 8; ++i) wreg[i] = __ldg((const float4*)(wsrc + koff) + i);
        #pragma unroll
        for (int i = 0; i < 2; ++i) xreg[i] = __ldg((const float4*)(xsrc + koff) + i);
    };
    auto cvt_slab = [&](int buf) {
        unsigned bb = sb + buf * BUF_SZ;
        unsigned wdst = bb + wrow * TSB + wf4 * 8;
        #pragma unroll
        for (int i = 0; i < 8; ++i) {
            unsigned h01, h23, l01, l23;
            cvt_hilo(wreg[i], h01, h23, l01, l23);
            sts8(wdst + WH_OFF + i * 8, h01, h23);
            sts8(wdst + WL_OFF + i * 8, l01, l23);
        }
        unsigned xdst = bb + xrow * TSB + xf4 * 8;
        #pragma unroll
        for (int i = 0; i < 2; ++i) {
            unsigned h01, h23, l01, l23;
            cvt_hilo(xreg[i], h01, h23, l01, l23);
            sts8(xdst + XH_OFF + i * 8, h01, h23);
            sts8(xdst + XL_OFF + i * 8, l01, l23);
        }
    };

    // fragment addressing (layout validated R6/R8; stride now 144B)
    unsigned aoff = (unsigned)((wid * 16 + (lane & 15)) * TSB + (lane >> 4) * 16);
    unsigned boff = (unsigned)(((lane & 7) + ((lane >> 3) & 1) * 8) * TSB + (lane >> 4) * 16);
    unsigned boff2 = boff + 16 * TSB;

    float acc[4][4];
    #pragma unroll
    for (int i = 0; i < 4; ++i)
        #pragma unroll
        for (int j = 0; j < 4; ++j) acc[i][j] = 0.f;

    ldg_slab(0);
    for (int s = 0; s < nslabs; ++s) {
        int buf = s & 1;
        cvt_slab(buf);
        __syncthreads();
        if (s + 1 < nslabs) ldg_slab(s + 1);

        unsigned bb = sb + buf * BUF_SZ;
        #pragma unroll
        for (int ks = 0; ks < 4; ++ks) {
            unsigned ko = ks * 32;
            unsigned ah0,ah1,ah2,ah3, al0,al1,al2,al3;
            unsigned p0,p1,p2,p3, q0,q1,q2,q3, r0,r1,r2,r3, s0,s1,s2,s3;
            ldsm4(ah0,ah1,ah2,ah3, bb + WH_OFF + aoff + ko);
            ldsm4(al0,al1,al2,al3, bb + WL_OFF + aoff + ko);
            ldsm4(p0,p1,p2,p3, bb + XH_OFF + boff  + ko);
            ldsm4(q0,q1,q2,q3, bb + XH_OFF + boff2 + ko);
            ldsm4(r0,r1,r2,r3, bb + XL_OFF + boff  + ko);
            ldsm4(s0,s1,s2,s3, bb + XL_OFF + boff2 + ko);
            mma16816(acc[0], ah0,ah1,ah2,ah3, p0,p2);
            mma16816(acc[0], ah0,ah1,ah2,ah3, r0,r2);
            mma16816(acc[0], al0,al1,al2,al3, p0,p2);
            mma16816(acc[1], ah0,ah1,ah2,ah3, p1,p3);
            mma16816(acc[1], ah0,ah1,ah2,ah3, r1,r3);
            mma16816(acc[1], al0,al1,al2,al3, p1,p3);
            mma16816(acc[2], ah0,ah1,ah2,ah3, q0,q2);
            mma16816(acc[2], ah0,ah1,ah2,ah3, s0,s2);
            mma16816(acc[2], al0,al1,al2,al3, q0,q2);
            mma16816(acc[3], ah0,ah1,ah2,ah3, q1,q3);
            mma16816(acc[3], ah0,ah1,ah2,ah3, s1,s3);
            mma16816(acc[3], al0,al1,al2,al3, q1,q3);
        }
    }

    // epilogue: split-K raw partials
    int g = lane >> 2, t = lane & 3;
    int n0 = tile * 128 + wid * 16 + g;
    #pragma unroll
    for (int nf = 0; nf < 4; ++nf) {
        int b0 = nf * 8 + 2 * t;
        g_part[(long)(ky * 32 + b0)     * N + n0]     = acc[nf][0];
        g_part[(long)(ky * 32 + b0 + 1) * N + n0]     = acc[nf][1];
        g_part[(long)(ky * 32 + b0)     * N + n0 + 8] = acc[nf][2];
        g_part[(long)(ky * 32 + b0 + 1) * N + n0 + 8] = acc[nf][3];
    }
    (void)outp;
}

// ---------------- split-K reduce + bias + relu ----------------
__global__ void reduce_kernel(const float* __restrict__ bias, int osel, int N, int ks) {
    int idx = blockIdx.x * 256 + threadIdx.x;
    if (idx >= 32 * N) return;
    float s = bias[idx % N];
    for (int si = 0; si < ks; ++si) s += g_part[(long)si * 32 * N + idx];
    float* out = (osel == 1) ? g_act1 : (osel == 2) ? g_act2 : g_act3;
    out[idx] = fmaxf(s, 0.f);
}

// ---------------- dense4 (4096 -> 64) ----------------
__global__ void dense4_kernel(const float* __restrict__ w4, const float* __restrict__ b4) {
    int n = blockIdx.x, tid = threadIdx.x;
    float acc[32];
    #pragma unroll
    for (int b = 0; b < 32; ++b) acc[b] = 0.f;
    const float* wr = w4 + n * 4096;
    for (int k = tid; k < 4096; k += 128) {
        float w = wr[k];
        #pragma unroll
        for (int b = 0; b < 32; ++b) acc[b] += g_act3[b * 4096 + k] * w;
    }
    __shared__ float red[4][32];
    int lane = tid & 31, wrp = tid >> 5;
    #pragma unroll
    for (int b = 0; b < 32; ++b) {
        float v = acc[b];
        v += __shfl_down_sync(0xffffffffu, v, 16);
        v += __shfl_down_sync(0xffffffffu, v, 8);
        v += __shfl_down_sync(0xffffffffu, v, 4);
        v += __shfl_down_sync(0xffffffffu, v, 2);
        v += __shfl_down_sync(0xffffffffu, v, 1);
        if (lane == 0) red[wrp][b] = v;
    }
    __syncthreads();
    if (tid < 32) {
        float s = red[0][tid] + red[1][tid] + red[2][tid] + red[3][tid] + b4[n];
        g_act4[tid * 64 + n] = fmaxf(s, 0.f);
    }
}

// ---------------- fused output (64 -> 16 -> 1) ----------------
__global__ void final_kernel(const float* __restrict__ wo, const float* __restrict__ bo,
                             const float* __restrict__ wf, const float* __restrict__ bf,
                             float* __restrict__ out) {
    int b = threadIdx.x;
    float res = bf[0];
    for (int j = 0; j < 16; ++j) {
        float o = bo[j];
        #pragma unroll
        for (int n = 0; n < 64; ++n) o += g_act4[b * 64 + n] * wo[j * 64 + n];
        res += o * wf[j];
    }
    out[b] = res;
}

extern "C" void kernel_launch(void* const* d_in, const int* in_sizes, int n_in,
                              void* d_out, int out_size) {
    const float* in  = (const float*)d_in[0];
    const float* cw  = (const float*)d_in[4];
    const float* cb  = (const float*)d_in[5];
    const float* w1  = (const float*)d_in[6];
    const float* b1  = (const float*)d_in[7];
    const float* w2  = (const float*)d_in[8];
    const float* b2  = (const float*)d_in[9];
    const float* w3  = (const float*)d_in[10];
    const float* b3  = (const float*)d_in[11];
    const float* w4  = (const float*)d_in[12];
    const float* b4  = (const float*)d_in[13];
    const float* wo  = (const float*)d_in[14];
    const float* bo  = (const float*)d_in[15];
    const float* wf  = (const float*)d_in[16];
    const float* bf  = (const float*)d_in[17];
    float* out = (float*)d_out;

    cudaFuncSetAttribute(gemm_mma, cudaFuncAttributeMaxDynamicSharedMemorySize, SMEM_TOTAL);

    conv_kernel<<<128, 128>>>(in, cw, cb);

    // dense1: 16384x21504 -> 128 tiles x split 2 = 256 CTAs, 168 slabs
    gemm_mma<<<dim3(128, 2), 256, SMEM_TOTAL>>>(0, w1, nullptr, 16384, 21504, 168);
    reduce_kernel<<<2048, 256>>>(b1, 1, 16384, 2);

    // dense2: 4096x16384 -> 32 tiles x split 8 = 256 CTAs, 32 slabs
    gemm_mma<<<dim3(32, 8), 256, SMEM_TOTAL>>>(1, w2, nullptr, 4096, 16384, 32);
    reduce_kernel<<<512, 256>>>(b2, 2, 4096, 8);

    // dense3: 4096x4096 -> 32 tiles x split 8 = 256 CTAs, 8 slabs
    gemm_mma<<<dim3(32, 8), 256, SMEM_TOTAL>>>(2, w3, nullptr, 4096, 4096, 8);
    reduce_kernel<<<512, 256>>>(b3, 3, 4096, 8);

    dense4_kernel<<<64, 128>>>(w4, b4);
    final_kernel<<<1, 32>>>(wo, bo, wf, bf, out);
}

// round 10
// speedup vs baseline: 1.2813x; 1.1256x over previous
#include <cuda_runtime.h>

// ---------------- device scratch ----------------
__device__ __align__(16) float g_act0[32 * 21504];
__device__ __align__(16) float g_act1[32 * 16384];
__device__ __align__(16) float g_act2[32 * 4096];
__device__ __align__(16) float g_act3[32 * 4096];
__device__ __align__(16) float g_act4[32 * 64];
__device__ __align__(16) float g_part[1048576];   // max(2*32*16384, 8*32*4096)

// ---------------- PTX helpers ----------------
__device__ __forceinline__ void mma16816(float* d, unsigned a0, unsigned a1, unsigned a2, unsigned a3,
                                         unsigned b0, unsigned b1) {
    asm volatile("mma.sync.aligned.m16n8k16.row.col.f32.bf16.bf16.f32 "
                 "{%0,%1,%2,%3}, {%4,%5,%6,%7}, {%8,%9}, {%0,%1,%2,%3};"
                 : "+f"(d[0]), "+f"(d[1]), "+f"(d[2]), "+f"(d[3])
                 : "r"(a0), "r"(a1), "r"(a2), "r"(a3), "r"(b0), "r"(b1));
}
// float2 -> packed bf16x2 hi + lo (hi = rn(v), lo = rn(v - hi))
__device__ __forceinline__ void cvt2(float2 v, unsigned &hi, unsigned &lo) {
    asm("cvt.rn.bf16x2.f32 %0, %1, %2;" : "=r"(hi) : "f"(v.y), "f"(v.x));
    float r0 = v.x - __uint_as_float(hi << 16);
    float r1 = v.y - __uint_as_float(hi & 0xffff0000u);
    asm("cvt.rn.bf16x2.f32 %0, %1, %2;" : "=r"(lo) : "f"(r1), "f"(r0));
}
__device__ __forceinline__ float2 ldg2(const float* p) {
    float2 v;
    asm volatile("ld.global.nc.v2.f32 {%0,%1}, [%2];" : "=f"(v.x), "=f"(v.y) : "l"(p));
    return v;
}

// ---------------- conv + permuted scatter ----------------
__global__ void conv_kernel(const float* __restrict__ in,
                            const float* __restrict__ cw,
                            const float* __restrict__ cb) {
    int b = blockIdx.x >> 2, f = blockIdx.x & 3, tid = threadIdx.x;
    __shared__ float xin[343], wsh[128], bsh[16];
    for (int i = tid; i < 343; i += 128) xin[i] = in[(b * 343 + i) * 5 + f];
    if (tid < 128) wsh[tid] = cw[tid];
    if (tid < 16)  bsh[tid] = cb[tid];
    __syncthreads();
    int h = b >> 4, base = (b & 15) * 1344 + f * 336;
    for (int l = tid; l < 336; l += 128) {
        #pragma unroll
        for (int c = 0; c < 16; ++c) {
            float s = bsh[c];
            #pragma unroll
            for (int k = 0; k < 8; ++k) s += xin[l + k] * wsh[c * 8 + k];
            g_act0[(2 * c + h) * 21504 + base + l] = fmaxf(s, 0.f);
        }
    }
}

// ---------------- bf16x3 mma.sync GEMM, LDG-direct fragments, no smem ----------------
// D[n,b] = sum_k W[n,k]*X[b,k]; tile M=128 x N=32, slab k=64, split-K partials.
__device__ __forceinline__ const float* act_in(int s) {
    return s == 0 ? g_act0 : s == 1 ? g_act1 : g_act2;
}

__global__ __launch_bounds__(256, 2)
void gemm_mma(int xsel, const float* __restrict__ W, int N, int K, int nslabs) {
    const float* X = act_in(xsel);
    int tid = threadIdx.x, wid = tid >> 5, lane = tid & 31;
    int tile = blockIdx.x, ky = blockIdx.y;
    int r = lane >> 2, kp = (lane & 3) * 2;
    long k0 = (long)ky * nslabs * 64 + kp;

    const float* wp = W + (long)(tile * 128 + wid * 16 + r) * K + k0;
    const float* xp = X + (long)r * K + k0;
    long K8 = 8L * K;

    float acc[4][4];
    #pragma unroll
    for (int i = 0; i < 4; ++i)
        #pragma unroll
        for (int j = 0; j < 4; ++j) acc[i][j] = 0.f;

    for (int s = 0; s < nslabs; ++s) {
        long sk = (long)s * 64;
        #pragma unroll
        for (int ks = 0; ks < 4; ++ks) {
            long ko = sk + ks * 16;
            // A fragment raw loads: (r,k),(r+8,k),(r,k+8),(r+8,k+8)
            float2 wa0 = ldg2(wp + ko);
            float2 wa1 = ldg2(wp + K8 + ko);
            float2 wa2 = ldg2(wp + ko + 8);
            float2 wa3 = ldg2(wp + K8 + ko + 8);
            // B fragment raw loads: n-groups 0..3 (n = nf*8 + r), k and k+8
            float2 xb0 = ldg2(xp + ko),           xb1 = ldg2(xp + ko + 8);
            float2 xb2 = ldg2(xp + K8 + ko),      xb3 = ldg2(xp + K8 + ko + 8);
            float2 xb4 = ldg2(xp + 2 * K8 + ko),  xb5 = ldg2(xp + 2 * K8 + ko + 8);
            float2 xb6 = ldg2(xp + 3 * K8 + ko),  xb7 = ldg2(xp + 3 * K8 + ko + 8);

            unsigned ah0, al0, ah1, al1, ah2, al2, ah3, al3;
            cvt2(wa0, ah0, al0); cvt2(wa1, ah1, al1);
            cvt2(wa2, ah2, al2); cvt2(wa3, ah3, al3);
            unsigned bh0, bl0, bh1, bl1, bh2, bl2, bh3, bl3;
            unsigned bh4, bl4, bh5, bl5, bh6, bl6, bh7, bl7;
            cvt2(xb0, bh0, bl0); cvt2(xb1, bh1, bl1);
            cvt2(xb2, bh2, bl2); cvt2(xb3, bh3, bl3);
            cvt2(xb4, bh4, bl4); cvt2(xb5, bh5, bl5);
            cvt2(xb6, bh6, bl6); cvt2(xb7, bh7, bl7);

            mma16816(acc[0], ah0, ah1, ah2, ah3, bh0, bh1);
            mma16816(acc[0], ah0, ah1, ah2, ah3, bl0, bl1);
            mma16816(acc[0], al0, al1, al2, al3, bh0, bh1);
            mma16816(acc[1], ah0, ah1, ah2, ah3, bh2, bh3);
            mma16816(acc[1], ah0, ah1, ah2, ah3, bl2, bl3);
            mma16816(acc[1], al0, al1, al2, al3, bh2, bh3);
            mma16816(acc[2], ah0, ah1, ah2, ah3, bh4, bh5);
            mma16816(acc[2], ah0, ah1, ah2, ah3, bl4, bl5);
            mma16816(acc[2], al0, al1, al2, al3, bh4, bh5);
            mma16816(acc[3], ah0, ah1, ah2, ah3, bh6, bh7);
            mma16816(acc[3], ah0, ah1, ah2, ah3, bl6, bl7);
            mma16816(acc[3], al0, al1, al2, al3, bh6, bh7);
        }
    }

    // epilogue: raw split-K partials; D frag rows r,r+8; cols 2t,2t+1 per n-group
    int t = lane & 3;
    int n0 = tile * 128 + wid * 16 + r;
    #pragma unroll
    for (int nf = 0; nf < 4; ++nf) {
        int b0 = nf * 8 + 2 * t;
        g_part[(long)(ky * 32 + b0)     * N + n0]     = acc[nf][0];
        g_part[(long)(ky * 32 + b0 + 1) * N + n0]     = acc[nf][1];
        g_part[(long)(ky * 32 + b0)     * N + n0 + 8] = acc[nf][2];
        g_part[(long)(ky * 32 + b0 + 1) * N + n0 + 8] = acc[nf][3];
    }
}

// ---------------- split-K reduce + bias + relu ----------------
__global__ void reduce_kernel(const float* __restrict__ bias, int osel, int N, int ks) {
    int idx = blockIdx.x * 256 + threadIdx.x;
    if (idx >= 32 * N) return;
    float s = bias[idx % N];
    for (int si = 0; si < ks; ++si) s += g_part[(long)si * 32 * N + idx];
    float* out = (osel == 1) ? g_act1 : (osel == 2) ? g_act2 : g_act3;
    out[idx] = fmaxf(s, 0.f);
}

// ---------------- dense4 (4096 -> 64) ----------------
__global__ void dense4_kernel(const float* __restrict__ w4, const float* __restrict__ b4) {
    int n = blockIdx.x, tid = threadIdx.x;
    float acc[32];
    #pragma unroll
    for (int b = 0; b < 32; ++b) acc[b] = 0.f;
    const float* wr = w4 + n * 4096;
    for (int k = tid; k < 4096; k += 128) {
        float w = wr[k];
        #pragma unroll
        for (int b = 0; b < 32; ++b) acc[b] += g_act3[b * 4096 + k] * w;
    }
    __shared__ float red[4][32];
    int lane = tid & 31, wrp = tid >> 5;
    #pragma unroll
    for (int b = 0; b < 32; ++b) {
        float v = acc[b];
        v += __shfl_down_sync(0xffffffffu, v, 16);
        v += __shfl_down_sync(0xffffffffu, v, 8);
        v += __shfl_down_sync(0xffffffffu, v, 4);
        v += __shfl_down_sync(0xffffffffu, v, 2);
        v += __shfl_down_sync(0xffffffffu, v, 1);
        if (lane == 0) red[wrp][b] = v;
    }
    __syncthreads();
    if (tid < 32) {
        float s = red[0][tid] + red[1][tid] + red[2][tid] + red[3][tid] + b4[n];
        g_act4[tid * 64 + n] = fmaxf(s, 0.f);
    }
}

// ---------------- fused output (64 -> 16 -> 1) ----------------
__global__ void final_kernel(const float* __restrict__ wo, const float* __restrict__ bo,
                             const float* __restrict__ wf, const float* __restrict__ bf,
                             float* __restrict__ out) {
    int b = threadIdx.x;
    float res = bf[0];
    for (int j = 0; j < 16; ++j) {
        float o = bo[j];
        #pragma unroll
        for (int n = 0; n < 64; ++n) o += g_act4[b * 64 + n] * wo[j * 64 + n];
        res += o * wf[j];
    }
    out[b] = res;
}

extern "C" void kernel_launch(void* const* d_in, const int* in_sizes, int n_in,
                              void* d_out, int out_size) {
    const float* in  = (const float*)d_in[0];
    const float* cw  = (const float*)d_in[4];
    const float* cb  = (const float*)d_in[5];
    const float* w1  = (const float*)d_in[6];
    const float* b1  = (const float*)d_in[7];
    const float* w2  = (const float*)d_in[8];
    const float* b2  = (const float*)d_in[9];
    const float* w3  = (const float*)d_in[10];
    const float* b3  = (const float*)d_in[11];
    const float* w4  = (const float*)d_in[12];
    const float* b4  = (const float*)d_in[13];
    const float* wo  = (const float*)d_in[14];
    const float* bo  = (const float*)d_in[15];
    const float* wf  = (const float*)d_in[16];
    const float* bf  = (const float*)d_in[17];
    float* out = (float*)d_out;

    conv_kernel<<<128, 128>>>(in, cw, cb);

    // dense1: 16384x21504 -> 128 tiles x split 2 = 256 CTAs, 168 slabs
    gemm_mma<<<dim3(128, 2), 256>>>(0, w1, 16384, 21504, 168);
    reduce_kernel<<<2048, 256>>>(b1, 1, 16384, 2);

    // dense2: 4096x16384 -> 32 tiles x split 8 = 256 CTAs, 32 slabs
    gemm_mma<<<dim3(32, 8), 256>>>(1, w2, 4096, 16384, 32);
    reduce_kernel<<<512, 256>>>(b2, 2, 4096, 8);

    // dense3: 4096x4096 -> 32 tiles x split 8 = 256 CTAs, 8 slabs
    gemm_mma<<<dim3(32, 8), 256>>>(2, w3, 4096, 4096, 8);
    reduce_kernel<<<512, 256>>>(b3, 3, 4096, 8);

    dense4_kernel<<<64, 128>>>(w4, b4);
    final_kernel<<<1, 32>>>(wo, bo, wf, bf, out);
}

// round 11
// speedup vs baseline: 2.3266x; 1.8157x over previous
#include <cuda_runtime.h>
#include <cstdint>

// ---------------- device scratch ----------------
__device__ __align__(16) float g_act0[32 * 21504];
__device__ __align__(16) float g_act3[32 * 4096];
__device__ __align__(16) float g_act4[32 * 64];
__device__ __align__(16) float g_part[1048576];        // max(2*32*16384, 8*32*4096)
__device__ __align__(16) uint4 g_xpk0[172032];         // 21504/16 * 128
__device__ __align__(16) uint4 g_xpk1[131072];         // 16384/16 * 128
__device__ __align__(16) uint4 g_xpk2[32768];          // 4096/16 * 128

// ---------------- PTX helpers ----------------
__device__ __forceinline__ void mma16816(float* d, unsigned a0, unsigned a1, unsigned a2, unsigned a3,
                                         unsigned b0, unsigned b1) {
    asm volatile("mma.sync.aligned.m16n8k16.row.col.f32.bf16.bf16.f32 "
                 "{%0,%1,%2,%3}, {%4,%5,%6,%7}, {%8,%9}, {%0,%1,%2,%3};"
                 : "+f"(d[0]), "+f"(d[1]), "+f"(d[2]), "+f"(d[3])
                 : "r"(a0), "r"(a1), "r"(a2), "r"(a3), "r"(b0), "r"(b1));
}
// float4 -> {hi01, hi23, lo01, lo23} packed bf16x2
__device__ __forceinline__ void cvt_hilo(float4 v, unsigned &h01, unsigned &h23,
                                         unsigned &l01, unsigned &l23) {
    asm("cvt.rn.bf16x2.f32 %0, %1, %2;" : "=r"(h01) : "f"(v.y), "f"(v.x));
    asm("cvt.rn.bf16x2.f32 %0, %1, %2;" : "=r"(h23) : "f"(v.w), "f"(v.z));
    float r0 = v.x - __uint_as_float(h01 << 16);
    float r1 = v.y - __uint_as_float(h01 & 0xffff0000u);
    float r2 = v.z - __uint_as_float(h23 << 16);
    float r3 = v.w - __uint_as_float(h23 & 0xffff0000u);
    asm("cvt.rn.bf16x2.f32 %0, %1, %2;" : "=r"(l01) : "f"(r1), "f"(r0));
    asm("cvt.rn.bf16x2.f32 %0, %1, %2;" : "=r"(l23) : "f"(r3), "f"(r2));
}

// ---------------- conv + permuted scatter ----------------
__global__ void conv_kernel(const float* __restrict__ in,
                            const float* __restrict__ cw,
                            const float* __restrict__ cb) {
    int b = blockIdx.x >> 2, f = blockIdx.x & 3, tid = threadIdx.x;
    __shared__ float xin[343], wsh[128], bsh[16];
    for (int i = tid; i < 343; i += 128) xin[i] = in[(b * 343 + i) * 5 + f];
    if (tid < 128) wsh[tid] = cw[tid];
    if (tid < 16)  bsh[tid] = cb[tid];
    __syncthreads();
    int h = b >> 4, base = (b & 15) * 1344 + f * 336;
    for (int l = tid; l < 336; l += 128) {
        #pragma unroll
        for (int c = 0; c < 16; ++c) {
            float s = bsh[c];
            #pragma unroll
            for (int k = 0; k < 8; ++k) s += xin[l + k] * wsh[c * 8 + k];
            g_act0[(2 * c + h) * 21504 + base + l] = fmaxf(s, 0.f);
        }
    }
}

// ---------------- pack fp32 X[32][K] -> fragment-ordered bf16 hi/lo uint4 ----------------
// uint4 index i: kb=i>>7, ng=(i>>5)&3, lane=i&31, r=lane>>2, t=lane&3
// source: row b=ng*8+r, cols kb*16 + t*4 .. +3
__global__ void pack_kernel(const float* __restrict__ src, int K, uint4* __restrict__ dst) {
    int i = blockIdx.x * 256 + threadIdx.x;
    if (i >= (K >> 4) * 128) return;
    int kb = i >> 7, ng = (i >> 5) & 3, lane = i & 31;
    int b = ng * 8 + (lane >> 2), c = kb * 16 + (lane & 3) * 4;
    float4 v = *(const float4*)(src + (long)b * K + c);
    uint4 o;
    cvt_hilo(v, o.x, o.y, o.z, o.w);
    dst[i] = o;
}

// ---------------- split-K reduce + bias + relu -> packed X ----------------
__global__ void reduce_pack(const float* __restrict__ bias, int N, int ks, uint4* __restrict__ dst) {
    int i = blockIdx.x * 256 + threadIdx.x;
    if (i >= (N >> 4) * 128) return;
    int kb = i >> 7, ng = (i >> 5) & 3, lane = i & 31;
    int b = ng * 8 + (lane >> 2), c = kb * 16 + (lane & 3) * 4;
    float4 s = *(const float4*)(bias + c);
    for (int si = 0; si < ks; ++si) {
        float4 p = *(const float4*)(g_part + ((long)(si * 32 + b)) * N + c);
        s.x += p.x; s.y += p.y; s.z += p.z; s.w += p.w;
    }
    s.x = fmaxf(s.x, 0.f); s.y = fmaxf(s.y, 0.f);
    s.z = fmaxf(s.z, 0.f); s.w = fmaxf(s.w, 0.f);
    uint4 o;
    cvt_hilo(s, o.x, o.y, o.z, o.w);
    dst[i] = o;
}

// ---------------- split-K reduce + bias + relu -> fp32 (for dense4 input) ----------------
__global__ void reduce_kernel(const float* __restrict__ bias, int N, int ks) {
    int idx = blockIdx.x * 256 + threadIdx.x;
    if (idx >= 32 * N) return;
    float s = bias[idx % N];
    for (int si = 0; si < ks; ++si) s += g_part[(long)si * 32 * N + idx];
    g_act3[idx] = fmaxf(s, 0.f);
}

// ---------------- bf16x3 mma.sync GEMM: LDG.128 W + prepacked X fragments ----------------
// D[n,b] = sum_k W[n,k]*X[b,k]; tile M=128 x N=32, slab k=64, split-K raw partials.
__global__ __launch_bounds__(256, 2)
void gemm_mma(const float* __restrict__ W, const uint4* __restrict__ xpk,
              int N, int K, int nslabs) {
    int tid = threadIdx.x, wid = tid >> 5, lane = tid & 31;
    int tile = blockIdx.x, ky = blockIdx.y;
    int r = lane >> 2, t = lane & 3;
    long k0 = (long)ky * nslabs * 64;

    const float* wp0 = W + (long)(tile * 128 + wid * 16 + r) * K + k0 + t * 4;
    const float* wp1 = wp0 + 8L * K;
    const uint4* xbase = xpk + (long)(ky * nslabs * 4) * 128 + lane;

    float acc[4][4];
    #pragma unroll
    for (int i = 0; i < 4; ++i)
        #pragma unroll
        for (int j = 0; j < 4; ++j) acc[i][j] = 0.f;

    for (int s = 0; s < nslabs; ++s) {
        long sk = (long)s * 64;
        #pragma unroll
        for (int ks = 0; ks < 4; ++ks) {
            float4 w0 = __ldg((const float4*)(wp0 + sk + ks * 16));
            float4 w1 = __ldg((const float4*)(wp1 + sk + ks * 16));
            unsigned a0h, a2h, a0l, a2l, a1h, a3h, a1l, a3l;
            cvt_hilo(w0, a0h, a2h, a0l, a2l);     // row r:   a0=(k01) a2=(k23)
            cvt_hilo(w1, a1h, a3h, a1l, a3l);     // row r+8
            const uint4* xq = xbase + (long)(s * 4 + ks) * 128;
            #pragma unroll
            for (int ng = 0; ng < 4; ++ng) {
                uint4 u = __ldg(xq + ng * 32);    // {bh0, bh1, bl0, bl1}
                mma16816(acc[ng], a0h, a1h, a2h, a3h, u.x, u.y);
                mma16816(acc[ng], a0h, a1h, a2h, a3h, u.z, u.w);
                mma16816(acc[ng], a0l, a1l, a2l, a3l, u.x, u.y);
            }
        }
    }

    // epilogue: raw split-K partials (mapping validated R10)
    int n0 = tile * 128 + wid * 16 + r;
    #pragma unroll
    for (int nf = 0; nf < 4; ++nf) {
        int b0 = nf * 8 + 2 * t;
        g_part[(long)(ky * 32 + b0)     * N + n0]     = acc[nf][0];
        g_part[(long)(ky * 32 + b0 + 1) * N + n0]     = acc[nf][1];
        g_part[(long)(ky * 32 + b0)     * N + n0 + 8] = acc[nf][2];
        g_part[(long)(ky * 32 + b0 + 1) * N + n0 + 8] = acc[nf][3];
    }
}

// ---------------- dense4 (4096 -> 64) ----------------
__global__ void dense4_kernel(const float* __restrict__ w4, const float* __restrict__ b4) {
    int n = blockIdx.x, tid = threadIdx.x;
    float acc[32];
    #pragma unroll
    for (int b = 0; b < 32; ++b) acc[b] = 0.f;
    const float* wr = w4 + n * 4096;
    for (int k = tid; k < 4096; k += 128) {
        float w = wr[k];
        #pragma unroll
        for (int b = 0; b < 32; ++b) acc[b] += g_act3[b * 4096 + k] * w;
    }
    __shared__ float red[4][32];
    int lane = tid & 31, wrp = tid >> 5;
    #pragma unroll
    for (int b = 0; b < 32; ++b) {
        float v = acc[b];
        v += __shfl_down_sync(0xffffffffu, v, 16);
        v += __shfl_down_sync(0xffffffffu, v, 8);
        v += __shfl_down_sync(0xffffffffu, v, 4);
        v += __shfl_down_sync(0xffffffffu, v, 2);
        v += __shfl_down_sync(0xffffffffu, v, 1);
        if (lane == 0) red[wrp][b] = v;
    }
    __syncthreads();
    if (tid < 32) {
        float s = red[0][tid] + red[1][tid] + red[2][tid] + red[3][tid] + b4[n];
        g_act4[tid * 64 + n] = fmaxf(s, 0.f);
    }
}

// ---------------- fused output (64 -> 16 -> 1) ----------------
__global__ void final_kernel(const float* __restrict__ wo, const float* __restrict__ bo,
                             const float* __restrict__ wf, const float* __restrict__ bf,
                             float* __restrict__ out) {
    int b = threadIdx.x;
    float res = bf[0];
    for (int j = 0; j < 16; ++j) {
        float o = bo[j];
        #pragma unroll
        for (int n = 0; n < 64; ++n) o += g_act4[b * 64 + n] * wo[j * 64 + n];
        res += o * wf[j];
    }
    out[b] = res;
}

extern "C" void kernel_launch(void* const* d_in, const int* in_sizes, int n_in,
                              void* d_out, int out_size) {
    const float* in  = (const float*)d_in[0];
    const float* cw  = (const float*)d_in[4];
    const float* cb  = (const float*)d_in[5];
    const float* w1  = (const float*)d_in[6];
    const float* b1  = (const float*)d_in[7];
    const float* w2  = (const float*)d_in[8];
    const float* b2  = (const float*)d_in[9];
    const float* w3  = (const float*)d_in[10];
    const float* b3  = (const float*)d_in[11];
    const float* w4  = (const float*)d_in[12];
    const float* b4  = (const float*)d_in[13];
    const float* wo  = (const float*)d_in[14];
    const float* bo  = (const float*)d_in[15];
    const float* wf  = (const float*)d_in[16];
    const float* bf  = (const float*)d_in[17];
    float* out = (float*)d_out;

    float *act0;
    uint4 *xpk0, *xpk1, *xpk2;
    cudaGetSymbolAddress((void**)&act0, g_act0);
    cudaGetSymbolAddress((void**)&xpk0, g_xpk0);
    cudaGetSymbolAddress((void**)&xpk1, g_xpk1);
    cudaGetSymbolAddress((void**)&xpk2, g_xpk2);

    conv_kernel<<<128, 128>>>(in, cw, cb);
    pack_kernel<<<672, 256>>>(act0, 21504, xpk0);

    // dense1: 16384x21504 -> 128 tiles x split 2, 168 slabs
    gemm_mma<<<dim3(128, 2), 256>>>(w1, xpk0, 16384, 21504, 168);
    reduce_pack<<<512, 256>>>(b1, 16384, 2, xpk1);

    // dense2: 4096x16384 -> 32 tiles x split 8, 32 slabs
    gemm_mma<<<dim3(32, 8), 256>>>(w2, xpk1, 4096, 16384, 32);
    reduce_pack<<<128, 256>>>(b2, 4096, 8, xpk2);

    // dense3: 4096x4096 -> 32 tiles x split 8, 8 slabs (fp32 out for dense4)
    gemm_mma<<<dim3(32, 8), 256>>>(w3, xpk2, 4096, 4096, 8);
    reduce_kernel<<<512, 256>>>(b3, 4096, 8);

    dense4_kernel<<<64, 128>>>(w4, b4);
    final_kernel<<<1, 32>>>(wo, bo, wf, bf, out);
}